// round 8
// baseline (speedup 1.0000x reference)
#include <cuda_runtime.h>
#include <math.h>

// Problem constants
#define B_   4
#define L_   2048
#define D_   1024
#define H_   16
#define DFF_ 4096
#define HD_  64
#define M_   (B_*L_)        // 8192 rows

// ---------------- scratch (static device arrays; no cudaMalloc) ----------------
__device__ float g_qkv[(size_t)M_ * 3 * D_];
__device__ float g_ctx[(size_t)M_ * D_];
__device__ float g_x1[(size_t)M_ * D_];
__device__ float g_h[(size_t)M_ * DFF_];
__device__ float g_t[(size_t)M_ * D_];

// ---------------- helpers ----------------
__device__ __forceinline__ unsigned f2tf(float x) {
    unsigned r;
    asm("cvt.rna.tf32.f32 %0, %1;" : "=r"(r) : "f"(x));
    return r;
}

__device__ __forceinline__ void mma_tf32(float* d, const unsigned* a, const unsigned* b) {
    asm volatile(
        "mma.sync.aligned.m16n8k8.row.col.f32.tf32.tf32.f32 "
        "{%0,%1,%2,%3}, {%4,%5,%6,%7}, {%8,%9}, {%0,%1,%2,%3};\n"
        : "+f"(d[0]), "+f"(d[1]), "+f"(d[2]), "+f"(d[3])
        : "r"(a[0]), "r"(a[1]), "r"(a[2]), "r"(a[3]), "r"(b[0]), "r"(b[1]));
}

template<int OP>
__device__ __forceinline__ float epi(float v, float b) {
    if (OP >= 1) v += b;
    if (OP == 2) v = 0.5f * v * (1.0f + erff(v * 0.7071067811865475f));
    return v;
}

// ---------------- TF32 GEMM (NN), 4 warps 64x64, double-buffered smem ----------------
// CTA tile 128x128, BK=32, ONE barrier per K-tile. Dynamic smem: 2 stages of
// (As 128x36 | Bs 32x136) words. STS for tile i+1 overlaps compute of tile i.
#define G_ASZ  (128*36)
#define G_BSZ  (32*136)
#define G_STG  (G_ASZ + G_BSZ)
#define G_SMEM (2 * G_STG * 4)

template<int OP>
__global__ void __launch_bounds__(128)
gemm_tf32(const float* __restrict__ A, const float* __restrict__ Bm,
          const float* __restrict__ bias, float* __restrict__ C,
          int K, int lda, int ldb, int ldc)
{
    extern __shared__ unsigned gsm[];

    const int t    = threadIdx.x;
    const int lane = t & 31;
    const int wid  = t >> 5;
    const int gid  = lane >> 2, tig = lane & 3;
    const int wm   = (wid & 1) * 64;
    const int wn   = (wid >> 1) * 64;
    const long bm0 = (long)blockIdx.y * 128;
    const long bn0 = (long)blockIdx.x * 128;

    float acc[4][8][4];
#pragma unroll
    for (int i = 0; i < 4; i++)
#pragma unroll
        for (int j = 0; j < 8; j++)
#pragma unroll
            for (int k = 0; k < 4; k++) acc[i][j][k] = 0.f;

    float4 av[8], bv[8];
    // prefetch tile 0 into regs, stage into buffer 0
#pragma unroll
    for (int i = 0; i < 8; i++) {
        int idx = t + i * 128;
        av[i] = *(const float4*)(A + (bm0 + (idx >> 3)) * lda + ((idx & 7) << 2));
        bv[i] = *(const float4*)(Bm + (long)(idx >> 5) * ldb + bn0 + ((idx & 31) << 2));
    }
    {
        unsigned* As = gsm;
        unsigned* Bs = gsm + G_ASZ;
#pragma unroll
        for (int i = 0; i < 8; i++) {
            int idx = t + i * 128;
            *(uint4*)&As[(idx >> 3) * 36 + ((idx & 7) << 2)] =
                make_uint4(f2tf(av[i].x), f2tf(av[i].y), f2tf(av[i].z), f2tf(av[i].w));
            *(uint4*)&Bs[(idx >> 5) * 136 + ((idx & 31) << 2)] =
                make_uint4(f2tf(bv[i].x), f2tf(bv[i].y), f2tf(bv[i].z), f2tf(bv[i].w));
        }
    }
    __syncthreads();

    const int NT = K >> 5;
    for (int it = 0; it < NT; it++) {
        const int s = it & 1;
        const unsigned* As = gsm + s * G_STG;
        const unsigned* Bs = gsm + s * G_STG + G_ASZ;
        const bool more = (it + 1 < NT);

        // issue next-tile global loads first (latency hidden behind kk0/kk1)
        if (more) {
            const int kn = (it + 1) << 5;
#pragma unroll
            for (int i = 0; i < 8; i++) {
                int idx = t + i * 128;
                av[i] = *(const float4*)(A + (bm0 + (idx >> 3)) * lda + kn + ((idx & 7) << 2));
                bv[i] = *(const float4*)(Bm + (long)(kn + (idx >> 5)) * ldb + bn0 + ((idx & 31) << 2));
            }
        }

#pragma unroll
        for (int kk = 0; kk < 4; kk++) {
            const int k = kk * 8;
            unsigned af[4][4];
#pragma unroll
            for (int mt = 0; mt < 4; mt++) {
                int r = wm + mt * 16 + gid;
                af[mt][0] = As[r * 36 + k + tig];
                af[mt][1] = As[(r + 8) * 36 + k + tig];
                af[mt][2] = As[r * 36 + k + tig + 4];
                af[mt][3] = As[(r + 8) * 36 + k + tig + 4];
            }
#pragma unroll
            for (int nt = 0; nt < 8; nt++) {
                unsigned bf[2];
                int cb = wn + nt * 8 + gid;
                bf[0] = Bs[(k + tig) * 136 + cb];
                bf[1] = Bs[(k + tig + 4) * 136 + cb];
#pragma unroll
                for (int mt = 0; mt < 4; mt++)
                    mma_tf32(acc[mt][nt], af[mt], bf);
            }
            // after kk1: stage next tile into the other buffer (overlaps kk2/kk3)
            if (kk == 1 && more) {
                unsigned* Ad = gsm + (s ^ 1) * G_STG;
                unsigned* Bd = gsm + (s ^ 1) * G_STG + G_ASZ;
#pragma unroll
                for (int i = 0; i < 8; i++) {
                    int idx = t + i * 128;
                    *(uint4*)&Ad[(idx >> 3) * 36 + ((idx & 7) << 2)] =
                        make_uint4(f2tf(av[i].x), f2tf(av[i].y), f2tf(av[i].z), f2tf(av[i].w));
                    *(uint4*)&Bd[(idx >> 5) * 136 + ((idx & 31) << 2)] =
                        make_uint4(f2tf(bv[i].x), f2tf(bv[i].y), f2tf(bv[i].z), f2tf(bv[i].w));
                }
            }
        }
        __syncthreads();
    }

#pragma unroll
    for (int mt = 0; mt < 4; mt++) {
#pragma unroll
        for (int nt = 0; nt < 8; nt++) {
            long r0 = bm0 + wm + mt * 16 + gid;
            long c0 = bn0 + wn + nt * 8 + tig * 2;
            float b0v = 0.f, b1v = 0.f;
            if (OP >= 1) { b0v = bias[c0]; b1v = bias[c0 + 1]; }
            float2 p0, p1;
            p0.x = epi<OP>(acc[mt][nt][0], b0v);
            p0.y = epi<OP>(acc[mt][nt][1], b1v);
            p1.x = epi<OP>(acc[mt][nt][2], b0v);
            p1.y = epi<OP>(acc[mt][nt][3], b1v);
            *(float2*)&C[r0 * ldc + c0]       = p0;
            *(float2*)&C[(r0 + 8) * ldc + c0] = p1;
        }
    }
}

// ---------------- fused flash attention ----------------
// 2 syncs per kv tile (top sync removed: Ks/bias writes of iter i only touch
// regions disjoint from the Ps/Vs reads still possible from iter i-1).
#define FA_KS_OFF 0
#define FA_VS_OFF (128*68)
#define FA_PS_OFF (FA_VS_OFF + 128*72)
#define FA_BI_OFF (FA_PS_OFF + 128*132)
#define FA_SMEM_BYTES ((FA_BI_OFF + 256) * 4)

extern __shared__ unsigned fa_sm[];

__global__ void __launch_bounds__(256)
flash_attn(const float* __restrict__ qkv, const float* __restrict__ bt,
           float* __restrict__ ctx)
{
    unsigned* Ks = fa_sm + FA_KS_OFF;
    unsigned* Vs = fa_sm + FA_VS_OFF;
    unsigned* Ps = fa_sm + FA_PS_OFF;
    float* bias_s = (float*)(fa_sm + FA_BI_OFF);

    const int z = blockIdx.y;
    const int b = z >> 4, h = z & 15;
    const int q0 = blockIdx.x * 128;
    const int t = threadIdx.x, lane = t & 31, wid = t >> 5;
    const int gid = lane >> 2, tig = lane & 3;
    const int wm = wid * 16;
    const int ld = 3 * D_;

    const float* Qg = qkv + (long)b * L_ * ld + (long)h * HD_;
    const float* Kg = Qg + D_;
    const float* Vg = Qg + 2 * D_;

    unsigned qf[8][4];
    {
        const float* r0p = Qg + (long)(q0 + wm + gid) * ld;
        const float* r1p = r0p + 8L * ld;
#pragma unroll
        for (int kk = 0; kk < 8; kk++) {
            qf[kk][0] = f2tf(r0p[kk * 8 + tig]);
            qf[kk][1] = f2tf(r1p[kk * 8 + tig]);
            qf[kk][2] = f2tf(r0p[kk * 8 + tig + 4]);
            qf[kk][3] = f2tf(r1p[kk * 8 + tig + 4]);
        }
    }

    float m0 = -1e30f, m1 = -1e30f, l0 = 0.f, l1 = 0.f;
    float o[8][4];
#pragma unroll
    for (int i = 0; i < 8; i++)
#pragma unroll
        for (int j = 0; j < 4; j++) o[i][j] = 0.f;

    float4 kv[8];
#pragma unroll
    for (int i = 0; i < 8; i++) {
        int idx = t + i * 256;
        kv[i] = *(const float4*)(Kg + (long)(idx >> 4) * ld + ((idx & 15) << 2));
    }

    for (int kt = 0; kt < 16; kt++) {
        // Ks / bias writes: disjoint from Ps/Vs still being read by slow warps
#pragma unroll
        for (int i = 0; i < 8; i++) {
            int idx = t + i * 256;
            *(uint4*)&Ks[(idx >> 4) * 68 + ((idx & 15) << 2)] =
                make_uint4(f2tf(kv[i].x), f2tf(kv[i].y), f2tf(kv[i].z), f2tf(kv[i].w));
        }
        if (t < 255) {
            int rel = kt * 128 - q0 + 384 + t;
            rel = min(max(rel, 0), 1022);
            bias_s[t] = bt[rel * 16 + h];
        }
        __syncthreads();

        {
            const float* Vt = Vg + (long)kt * 128 * ld;
#pragma unroll
            for (int i = 0; i < 8; i++) {
                int idx = t + i * 256;
                kv[i] = *(const float4*)(Vt + (long)(idx >> 4) * ld + ((idx & 15) << 2));
            }
        }

        float s[16][4];
#pragma unroll
        for (int i = 0; i < 16; i++)
#pragma unroll
            for (int j = 0; j < 4; j++) s[i][j] = 0.f;
#pragma unroll
        for (int kk = 0; kk < 8; kk++) {
            const int k = kk * 8;
#pragma unroll
            for (int nt = 0; nt < 16; nt++) {
                unsigned bf[2];
                int cb = nt * 8 + gid;
                bf[0] = Ks[cb * 68 + k + tig];
                bf[1] = Ks[cb * 68 + k + tig + 4];
                mma_tf32(s[nt], qf[kk], bf);
            }
        }

        float mx0 = -1e30f, mx1 = -1e30f;
        const int jb0 = 2 * tig - wm - gid + 127;
#pragma unroll
        for (int nt = 0; nt < 16; nt++) {
            int j0 = jb0 + nt * 8;
            s[nt][0] = s[nt][0] * 0.125f + bias_s[j0];
            s[nt][1] = s[nt][1] * 0.125f + bias_s[j0 + 1];
            s[nt][2] = s[nt][2] * 0.125f + bias_s[j0 - 8];
            s[nt][3] = s[nt][3] * 0.125f + bias_s[j0 - 7];
            mx0 = fmaxf(mx0, fmaxf(s[nt][0], s[nt][1]));
            mx1 = fmaxf(mx1, fmaxf(s[nt][2], s[nt][3]));
        }
        mx0 = fmaxf(mx0, __shfl_xor_sync(0xffffffffu, mx0, 1));
        mx0 = fmaxf(mx0, __shfl_xor_sync(0xffffffffu, mx0, 2));
        mx1 = fmaxf(mx1, __shfl_xor_sync(0xffffffffu, mx1, 1));
        mx1 = fmaxf(mx1, __shfl_xor_sync(0xffffffffu, mx1, 2));

        float mn0 = fmaxf(m0, mx0), mn1 = fmaxf(m1, mx1);
        float a0 = __expf(m0 - mn0), a1 = __expf(m1 - mn1);
        m0 = mn0; m1 = mn1;

        float sum0 = 0.f, sum1 = 0.f;
#pragma unroll
        for (int nt = 0; nt < 16; nt++) {
            s[nt][0] = __expf(s[nt][0] - mn0);
            s[nt][1] = __expf(s[nt][1] - mn0);
            s[nt][2] = __expf(s[nt][2] - mn1);
            s[nt][3] = __expf(s[nt][3] - mn1);
            sum0 += s[nt][0] + s[nt][1];
            sum1 += s[nt][2] + s[nt][3];
        }
        sum0 += __shfl_xor_sync(0xffffffffu, sum0, 1);
        sum0 += __shfl_xor_sync(0xffffffffu, sum0, 2);
        sum1 += __shfl_xor_sync(0xffffffffu, sum1, 1);
        sum1 += __shfl_xor_sync(0xffffffffu, sum1, 2);
        l0 = l0 * a0 + sum0;
        l1 = l1 * a1 + sum1;
#pragma unroll
        for (int nt = 0; nt < 8; nt++) {
            o[nt][0] *= a0; o[nt][1] *= a0;
            o[nt][2] *= a1; o[nt][3] *= a1;
        }

        {
            const int r0 = (wm + gid) * 132, r1 = (wm + gid + 8) * 132;
#pragma unroll
            for (int nt = 0; nt < 16; nt++) {
                int c = nt * 8 + 2 * tig;
                *(uint2*)&Ps[r0 + c] = make_uint2(f2tf(s[nt][0]), f2tf(s[nt][1]));
                *(uint2*)&Ps[r1 + c] = make_uint2(f2tf(s[nt][2]), f2tf(s[nt][3]));
            }
        }
#pragma unroll
        for (int i = 0; i < 8; i++) {
            int idx = t + i * 256;
            *(uint4*)&Vs[(idx >> 4) * 72 + ((idx & 15) << 2)] =
                make_uint4(f2tf(kv[i].x), f2tf(kv[i].y), f2tf(kv[i].z), f2tf(kv[i].w));
        }
        __syncthreads();

        if (kt < 15) {
            const float* Kt = Kg + (long)(kt + 1) * 128 * ld;
#pragma unroll
            for (int i = 0; i < 8; i++) {
                int idx = t + i * 256;
                kv[i] = *(const float4*)(Kt + (long)(idx >> 4) * ld + ((idx & 15) << 2));
            }
        }

#pragma unroll
        for (int kk = 0; kk < 16; kk++) {
            const int k = kk * 8;
            unsigned af[4];
            af[0] = Ps[(wm + gid) * 132 + k + tig];
            af[1] = Ps[(wm + gid + 8) * 132 + k + tig];
            af[2] = Ps[(wm + gid) * 132 + k + tig + 4];
            af[3] = Ps[(wm + gid + 8) * 132 + k + tig + 4];
#pragma unroll
            for (int nt = 0; nt < 8; nt++) {
                unsigned bf[2];
                int cb = nt * 8 + gid;
                bf[0] = Vs[(k + tig) * 72 + cb];
                bf[1] = Vs[(k + tig + 4) * 72 + cb];
                mma_tf32(o[nt], af, bf);
            }
        }
    }

    const float inv0 = 1.0f / l0, inv1 = 1.0f / l1;
    float* C0 = ctx + ((long)b * L_ + q0 + wm + gid) * D_ + h * HD_;
    float* C1 = C0 + 8L * D_;
#pragma unroll
    for (int nt = 0; nt < 8; nt++) {
        int c = nt * 8 + 2 * tig;
        *(float2*)&C0[c] = make_float2(o[nt][0] * inv0, o[nt][1] * inv0);
        *(float2*)&C1[c] = make_float2(o[nt][2] * inv1, o[nt][3] * inv1);
    }
}

// ---------------- residual add + LayerNorm ----------------
__global__ void __launch_bounds__(256)
add_ln(const float* __restrict__ X, const float* __restrict__ Y,
       const float* __restrict__ gamma, const float* __restrict__ beta,
       float* __restrict__ O)
{
    const long r = blockIdx.x;
    const int t = threadIdx.x;
    __shared__ float red[16];

    float4 a = *(const float4*)(X + r * D_ + t * 4);
    float4 b = *(const float4*)(Y + r * D_ + t * 4);
    float v[4] = {a.x + b.x, a.y + b.y, a.z + b.z, a.w + b.w};

    float s = v[0] + v[1] + v[2] + v[3];
    float s2 = v[0]*v[0] + v[1]*v[1] + v[2]*v[2] + v[3]*v[3];
#pragma unroll
    for (int off = 16; off > 0; off >>= 1) {
        s  += __shfl_xor_sync(0xffffffffu, s, off);
        s2 += __shfl_xor_sync(0xffffffffu, s2, off);
    }
    if ((t & 31) == 0) { red[t >> 5] = s; red[8 + (t >> 5)] = s2; }
    __syncthreads();
    float S = 0.f, S2 = 0.f;
#pragma unroll
    for (int i = 0; i < 8; i++) { S += red[i]; S2 += red[8 + i]; }
    const float mean = S * (1.0f / D_);
    const float var  = S2 * (1.0f / D_) - mean * mean;
    const float rinv = rsqrtf(var + 1e-5f);

    float4 g  = *(const float4*)(gamma + t * 4);
    float4 be = *(const float4*)(beta + t * 4);
    float4 o;
    o.x = (v[0] - mean) * rinv * g.x + be.x;
    o.y = (v[1] - mean) * rinv * g.y + be.y;
    o.z = (v[2] - mean) * rinv * g.z + be.z;
    o.w = (v[3] - mean) * rinv * g.w + be.w;
    *(float4*)(O + r * D_ + t * 4) = o;
}

// ---------------- launcher ----------------
extern "C" void kernel_launch(void* const* d_in, const int* in_sizes, int n_in,
                              void* d_out, int out_size)
{
    const float* x     = (const float*)d_in[0];
    const float* w_qkv = (const float*)d_in[1];
    const float* w_out = (const float*)d_in[2];
    const float* b_out = (const float*)d_in[3];
    const float* bt    = (const float*)d_in[4];
    const float* g1    = (const float*)d_in[5];
    const float* be1   = (const float*)d_in[6];
    const float* w1    = (const float*)d_in[7];
    const float* bf1   = (const float*)d_in[8];
    const float* w2    = (const float*)d_in[9];
    const float* bf2   = (const float*)d_in[10];
    const float* g2    = (const float*)d_in[11];
    const float* be2   = (const float*)d_in[12];
    float* out = (float*)d_out;

    float *qkv, *ctx, *x1, *hh, *tt;
    cudaGetSymbolAddress((void**)&qkv, g_qkv);
    cudaGetSymbolAddress((void**)&ctx, g_ctx);
    cudaGetSymbolAddress((void**)&x1,  g_x1);
    cudaGetSymbolAddress((void**)&hh,  g_h);
    cudaGetSymbolAddress((void**)&tt,  g_t);

    cudaFuncSetAttribute(flash_attn, cudaFuncAttributeMaxDynamicSharedMemorySize,
                         FA_SMEM_BYTES);
    cudaFuncSetAttribute(gemm_tf32<0>, cudaFuncAttributeMaxDynamicSharedMemorySize, G_SMEM);
    cudaFuncSetAttribute(gemm_tf32<1>, cudaFuncAttributeMaxDynamicSharedMemorySize, G_SMEM);
    cudaFuncSetAttribute(gemm_tf32<2>, cudaFuncAttributeMaxDynamicSharedMemorySize, G_SMEM);

    // 1) qkv = x @ w_qkv
    gemm_tf32<0><<<dim3(3 * D_ / 128, M_ / 128), 128, G_SMEM>>>(
        x, w_qkv, nullptr, qkv, D_, D_, 3 * D_, 3 * D_);

    // 2) fused attention -> ctx
    flash_attn<<<dim3(L_ / 128, B_ * H_), 256, FA_SMEM_BYTES>>>(qkv, bt, ctx);

    // 3) attn_out = ctx @ w_out + b_out
    gemm_tf32<1><<<dim3(D_ / 128, M_ / 128), 128, G_SMEM>>>(
        ctx, w_out, b_out, tt, D_, D_, D_, D_);

    // 4) x1 = LN(x + attn_out)
    add_ln<<<M_, 256>>>(x, tt, g1, be1, x1);

    // 5) h = gelu(x1 @ w_ff1 + b_ff1)
    gemm_tf32<2><<<dim3(DFF_ / 128, M_ / 128), 128, G_SMEM>>>(
        x1, w1, bf1, hh, D_, D_, DFF_, DFF_);

    // 6) ffn_out = h @ w_ff2 + b_ff2
    gemm_tf32<1><<<dim3(D_ / 128, M_ / 128), 128, G_SMEM>>>(
        hh, w2, bf2, tt, DFF_, DFF_, D_, D_);

    // 7) out = LN(x1 + ffn_out)
    add_ln<<<M_, 256>>>(x1, tt, g2, be2, out);
}

// round 9
// speedup vs baseline: 1.1422x; 1.1422x over previous
#include <cuda_runtime.h>
#include <math.h>

// Problem constants
#define B_   4
#define L_   2048
#define D_   1024
#define H_   16
#define DFF_ 4096
#define HD_  64
#define M_   (B_*L_)        // 8192 rows

// ---------------- scratch (static device arrays; no cudaMalloc) ----------------
__device__ float g_qkv[(size_t)M_ * 3 * D_];
__device__ float g_ctx[(size_t)M_ * D_];
__device__ float g_x1[(size_t)M_ * D_];
__device__ float g_h[(size_t)M_ * DFF_];
__device__ float g_t[(size_t)M_ * D_];

// ---------------- helpers ----------------
__device__ __forceinline__ unsigned f2tf(float x) {
    unsigned r;
    asm("cvt.rna.tf32.f32 %0, %1;" : "=r"(r) : "f"(x));
    return r;
}

__device__ __forceinline__ void mma_tf32(float* d, const unsigned* a, const unsigned* b) {
    asm volatile(
        "mma.sync.aligned.m16n8k8.row.col.f32.tf32.tf32.f32 "
        "{%0,%1,%2,%3}, {%4,%5,%6,%7}, {%8,%9}, {%0,%1,%2,%3};\n"
        : "+f"(d[0]), "+f"(d[1]), "+f"(d[2]), "+f"(d[3])
        : "r"(a[0]), "r"(a[1]), "r"(a[2]), "r"(a[3]), "r"(b[0]), "r"(b[1]));
}

template<int OP>
__device__ __forceinline__ float epi(float v, float b) {
    if (OP >= 1) v += b;
    if (OP == 2) v = 0.5f * v * (1.0f + erff(v * 0.7071067811865475f));
    return v;
}

// ---------------- TF32 GEMM (NN), 4 warps, warp tile 64x64 (R7 proven) ----------------
template<int OP>
__global__ void __launch_bounds__(128)
gemm_tf32(const float* __restrict__ A, const float* __restrict__ Bm,
          const float* __restrict__ bias, float* __restrict__ C,
          int K, int lda, int ldb, int ldc)
{
    constexpr int ASR = 36;
    constexpr int BSR = 136;

    __shared__ unsigned As[128 * ASR];
    __shared__ unsigned Bs[32 * BSR];

    const int t    = threadIdx.x;
    const int lane = t & 31;
    const int wid  = t >> 5;
    const int gid  = lane >> 2, tig = lane & 3;
    const int wm   = (wid & 1) * 64;
    const int wn   = (wid >> 1) * 64;
    const long bm0 = (long)blockIdx.y * 128;
    const long bn0 = (long)blockIdx.x * 128;

    float acc[4][8][4];
#pragma unroll
    for (int i = 0; i < 4; i++)
#pragma unroll
        for (int j = 0; j < 8; j++)
#pragma unroll
            for (int k = 0; k < 4; k++) acc[i][j][k] = 0.f;

    float4 av[8], bv[8];
    // prefetch tile 0
#pragma unroll
    for (int i = 0; i < 8; i++) {
        int idx = t + i * 128;
        av[i] = *(const float4*)(A + (bm0 + (idx >> 3)) * lda + ((idx & 7) << 2));
        bv[i] = *(const float4*)(Bm + (long)(idx >> 5) * ldb + bn0 + ((idx & 31) << 2));
    }

    for (int k0 = 0; k0 < K; k0 += 32) {
        __syncthreads();
#pragma unroll
        for (int i = 0; i < 8; i++) {
            int idx = t + i * 128;
            *(uint4*)&As[(idx >> 3) * ASR + ((idx & 7) << 2)] =
                make_uint4(f2tf(av[i].x), f2tf(av[i].y), f2tf(av[i].z), f2tf(av[i].w));
            *(uint4*)&Bs[(idx >> 5) * BSR + ((idx & 31) << 2)] =
                make_uint4(f2tf(bv[i].x), f2tf(bv[i].y), f2tf(bv[i].z), f2tf(bv[i].w));
        }
        __syncthreads();
        if (k0 + 32 < K) {
            const int kn = k0 + 32;
#pragma unroll
            for (int i = 0; i < 8; i++) {
                int idx = t + i * 128;
                av[i] = *(const float4*)(A + (bm0 + (idx >> 3)) * lda + kn + ((idx & 7) << 2));
                bv[i] = *(const float4*)(Bm + (long)(kn + (idx >> 5)) * ldb + bn0 + ((idx & 31) << 2));
            }
        }
#pragma unroll
        for (int kk = 0; kk < 4; kk++) {
            const int k = kk * 8;
            unsigned af[4][4];
#pragma unroll
            for (int mt = 0; mt < 4; mt++) {
                int r = wm + mt * 16 + gid;
                af[mt][0] = As[r * ASR + k + tig];
                af[mt][1] = As[(r + 8) * ASR + k + tig];
                af[mt][2] = As[r * ASR + k + tig + 4];
                af[mt][3] = As[(r + 8) * ASR + k + tig + 4];
            }
#pragma unroll
            for (int nt = 0; nt < 8; nt++) {
                unsigned bf[2];
                int cb = wn + nt * 8 + gid;
                bf[0] = Bs[(k + tig) * BSR + cb];
                bf[1] = Bs[(k + tig + 4) * BSR + cb];
#pragma unroll
                for (int mt = 0; mt < 4; mt++)
                    mma_tf32(acc[mt][nt], af[mt], bf);
            }
        }
    }

#pragma unroll
    for (int mt = 0; mt < 4; mt++) {
#pragma unroll
        for (int nt = 0; nt < 8; nt++) {
            long r0 = bm0 + wm + mt * 16 + gid;
            long c0 = bn0 + wn + nt * 8 + tig * 2;
            float b0v = 0.f, b1v = 0.f;
            if (OP >= 1) { b0v = bias[c0]; b1v = bias[c0 + 1]; }
            float2 p0, p1;
            p0.x = epi<OP>(acc[mt][nt][0], b0v);
            p0.y = epi<OP>(acc[mt][nt][1], b1v);
            p1.x = epi<OP>(acc[mt][nt][2], b0v);
            p1.y = epi<OP>(acc[mt][nt][3], b1v);
            *(float2*)&C[r0 * ldc + c0]       = p0;
            *(float2*)&C[(r0 + 8) * ldc + c0] = p1;
        }
    }
}

// ---------------- fused flash attention (2 syncs per kv tile) ----------------
// Top-of-loop sync removed: Ks/bias writes of iter i are disjoint from Ps/Vs
// reads of iter i-1; each warp's own PV reads precede its K stores in program order.
#define FA_KS_OFF 0
#define FA_VS_OFF (128*68)
#define FA_PS_OFF (FA_VS_OFF + 128*72)
#define FA_BI_OFF (FA_PS_OFF + 128*132)
#define FA_SMEM_BYTES ((FA_BI_OFF + 256) * 4)

extern __shared__ unsigned fa_sm[];

__global__ void __launch_bounds__(256)
flash_attn(const float* __restrict__ qkv, const float* __restrict__ bt,
           float* __restrict__ ctx)
{
    unsigned* Ks = fa_sm + FA_KS_OFF;
    unsigned* Vs = fa_sm + FA_VS_OFF;
    unsigned* Ps = fa_sm + FA_PS_OFF;
    float* bias_s = (float*)(fa_sm + FA_BI_OFF);

    const int z = blockIdx.y;
    const int b = z >> 4, h = z & 15;
    const int q0 = blockIdx.x * 128;
    const int t = threadIdx.x, lane = t & 31, wid = t >> 5;
    const int gid = lane >> 2, tig = lane & 3;
    const int wm = wid * 16;
    const int ld = 3 * D_;

    const float* Qg = qkv + (long)b * L_ * ld + (long)h * HD_;
    const float* Kg = Qg + D_;
    const float* Vg = Qg + 2 * D_;

    unsigned qf[8][4];
    {
        const float* r0p = Qg + (long)(q0 + wm + gid) * ld;
        const float* r1p = r0p + 8L * ld;
#pragma unroll
        for (int kk = 0; kk < 8; kk++) {
            qf[kk][0] = f2tf(r0p[kk * 8 + tig]);
            qf[kk][1] = f2tf(r1p[kk * 8 + tig]);
            qf[kk][2] = f2tf(r0p[kk * 8 + tig + 4]);
            qf[kk][3] = f2tf(r1p[kk * 8 + tig + 4]);
        }
    }

    float m0 = -1e30f, m1 = -1e30f, l0 = 0.f, l1 = 0.f;
    float o[8][4];
#pragma unroll
    for (int i = 0; i < 8; i++)
#pragma unroll
        for (int j = 0; j < 4; j++) o[i][j] = 0.f;

    float4 kv[8];
#pragma unroll
    for (int i = 0; i < 8; i++) {
        int idx = t + i * 256;
        kv[i] = *(const float4*)(Kg + (long)(idx >> 4) * ld + ((idx & 15) << 2));
    }

    for (int kt = 0; kt < 16; kt++) {
        // Ks / bias writes (no leading sync needed; regions disjoint from prior reads)
#pragma unroll
        for (int i = 0; i < 8; i++) {
            int idx = t + i * 256;
            *(uint4*)&Ks[(idx >> 4) * 68 + ((idx & 15) << 2)] =
                make_uint4(f2tf(kv[i].x), f2tf(kv[i].y), f2tf(kv[i].z), f2tf(kv[i].w));
        }
        if (t < 255) {
            int rel = kt * 128 - q0 + 384 + t;
            rel = min(max(rel, 0), 1022);
            bias_s[t] = bt[rel * 16 + h];
        }
        __syncthreads();

        {
            const float* Vt = Vg + (long)kt * 128 * ld;
#pragma unroll
            for (int i = 0; i < 8; i++) {
                int idx = t + i * 256;
                kv[i] = *(const float4*)(Vt + (long)(idx >> 4) * ld + ((idx & 15) << 2));
            }
        }

        float s[16][4];
#pragma unroll
        for (int i = 0; i < 16; i++)
#pragma unroll
            for (int j = 0; j < 4; j++) s[i][j] = 0.f;
#pragma unroll
        for (int kk = 0; kk < 8; kk++) {
            const int k = kk * 8;
#pragma unroll
            for (int nt = 0; nt < 16; nt++) {
                unsigned bf[2];
                int cb = nt * 8 + gid;
                bf[0] = Ks[cb * 68 + k + tig];
                bf[1] = Ks[cb * 68 + k + tig + 4];
                mma_tf32(s[nt], qf[kk], bf);
            }
        }

        float mx0 = -1e30f, mx1 = -1e30f;
        const int jb0 = 2 * tig - wm - gid + 127;
#pragma unroll
        for (int nt = 0; nt < 16; nt++) {
            int j0 = jb0 + nt * 8;
            s[nt][0] = s[nt][0] * 0.125f + bias_s[j0];
            s[nt][1] = s[nt][1] * 0.125f + bias_s[j0 + 1];
            s[nt][2] = s[nt][2] * 0.125f + bias_s[j0 - 8];
            s[nt][3] = s[nt][3] * 0.125f + bias_s[j0 - 7];
            mx0 = fmaxf(mx0, fmaxf(s[nt][0], s[nt][1]));
            mx1 = fmaxf(mx1, fmaxf(s[nt][2], s[nt][3]));
        }
        mx0 = fmaxf(mx0, __shfl_xor_sync(0xffffffffu, mx0, 1));
        mx0 = fmaxf(mx0, __shfl_xor_sync(0xffffffffu, mx0, 2));
        mx1 = fmaxf(mx1, __shfl_xor_sync(0xffffffffu, mx1, 1));
        mx1 = fmaxf(mx1, __shfl_xor_sync(0xffffffffu, mx1, 2));

        float mn0 = fmaxf(m0, mx0), mn1 = fmaxf(m1, mx1);
        float a0 = __expf(m0 - mn0), a1 = __expf(m1 - mn1);
        m0 = mn0; m1 = mn1;

        float sum0 = 0.f, sum1 = 0.f;
#pragma unroll
        for (int nt = 0; nt < 16; nt++) {
            s[nt][0] = __expf(s[nt][0] - mn0);
            s[nt][1] = __expf(s[nt][1] - mn0);
            s[nt][2] = __expf(s[nt][2] - mn1);
            s[nt][3] = __expf(s[nt][3] - mn1);
            sum0 += s[nt][0] + s[nt][1];
            sum1 += s[nt][2] + s[nt][3];
        }
        sum0 += __shfl_xor_sync(0xffffffffu, sum0, 1);
        sum0 += __shfl_xor_sync(0xffffffffu, sum0, 2);
        sum1 += __shfl_xor_sync(0xffffffffu, sum1, 1);
        sum1 += __shfl_xor_sync(0xffffffffu, sum1, 2);
        l0 = l0 * a0 + sum0;
        l1 = l1 * a1 + sum1;
#pragma unroll
        for (int nt = 0; nt < 8; nt++) {
            o[nt][0] *= a0; o[nt][1] *= a0;
            o[nt][2] *= a1; o[nt][3] *= a1;
        }

        {
            const int r0 = (wm + gid) * 132, r1 = (wm + gid + 8) * 132;
#pragma unroll
            for (int nt = 0; nt < 16; nt++) {
                int c = nt * 8 + 2 * tig;
                *(uint2*)&Ps[r0 + c] = make_uint2(f2tf(s[nt][0]), f2tf(s[nt][1]));
                *(uint2*)&Ps[r1 + c] = make_uint2(f2tf(s[nt][2]), f2tf(s[nt][3]));
            }
        }
#pragma unroll
        for (int i = 0; i < 8; i++) {
            int idx = t + i * 256;
            *(uint4*)&Vs[(idx >> 4) * 72 + ((idx & 15) << 2)] =
                make_uint4(f2tf(kv[i].x), f2tf(kv[i].y), f2tf(kv[i].z), f2tf(kv[i].w));
        }
        __syncthreads();

        if (kt < 15) {
            const float* Kt = Kg + (long)(kt + 1) * 128 * ld;
#pragma unroll
            for (int i = 0; i < 8; i++) {
                int idx = t + i * 256;
                kv[i] = *(const float4*)(Kt + (long)(idx >> 4) * ld + ((idx & 15) << 2));
            }
        }

#pragma unroll
        for (int kk = 0; kk < 16; kk++) {
            const int k = kk * 8;
            unsigned af[4];
            af[0] = Ps[(wm + gid) * 132 + k + tig];
            af[1] = Ps[(wm + gid + 8) * 132 + k + tig];
            af[2] = Ps[(wm + gid) * 132 + k + tig + 4];
            af[3] = Ps[(wm + gid + 8) * 132 + k + tig + 4];
#pragma unroll
            for (int nt = 0; nt < 8; nt++) {
                unsigned bf[2];
                int cb = nt * 8 + gid;
                bf[0] = Vs[(k + tig) * 72 + cb];
                bf[1] = Vs[(k + tig + 4) * 72 + cb];
                mma_tf32(o[nt], af, bf);
            }
        }
    }

    const float inv0 = 1.0f / l0, inv1 = 1.0f / l1;
    float* C0 = ctx + ((long)b * L_ + q0 + wm + gid) * D_ + h * HD_;
    float* C1 = C0 + 8L * D_;
#pragma unroll
    for (int nt = 0; nt < 8; nt++) {
        int c = nt * 8 + 2 * tig;
        *(float2*)&C0[c] = make_float2(o[nt][0] * inv0, o[nt][1] * inv0);
        *(float2*)&C1[c] = make_float2(o[nt][2] * inv1, o[nt][3] * inv1);
    }
}

// ---------------- residual add + LayerNorm ----------------
__global__ void __launch_bounds__(256)
add_ln(const float* __restrict__ X, const float* __restrict__ Y,
       const float* __restrict__ gamma, const float* __restrict__ beta,
       float* __restrict__ O)
{
    const long r = blockIdx.x;
    const int t = threadIdx.x;
    __shared__ float red[16];

    float4 a = *(const float4*)(X + r * D_ + t * 4);
    float4 b = *(const float4*)(Y + r * D_ + t * 4);
    float v[4] = {a.x + b.x, a.y + b.y, a.z + b.z, a.w + b.w};

    float s = v[0] + v[1] + v[2] + v[3];
    float s2 = v[0]*v[0] + v[1]*v[1] + v[2]*v[2] + v[3]*v[3];
#pragma unroll
    for (int off = 16; off > 0; off >>= 1) {
        s  += __shfl_xor_sync(0xffffffffu, s, off);
        s2 += __shfl_xor_sync(0xffffffffu, s2, off);
    }
    if ((t & 31) == 0) { red[t >> 5] = s; red[8 + (t >> 5)] = s2; }
    __syncthreads();
    float S = 0.f, S2 = 0.f;
#pragma unroll
    for (int i = 0; i < 8; i++) { S += red[i]; S2 += red[8 + i]; }
    const float mean = S * (1.0f / D_);
    const float var  = S2 * (1.0f / D_) - mean * mean;
    const float rinv = rsqrtf(var + 1e-5f);

    float4 g  = *(const float4*)(gamma + t * 4);
    float4 be = *(const float4*)(beta + t * 4);
    float4 o;
    o.x = (v[0] - mean) * rinv * g.x + be.x;
    o.y = (v[1] - mean) * rinv * g.y + be.y;
    o.z = (v[2] - mean) * rinv * g.z + be.z;
    o.w = (v[3] - mean) * rinv * g.w + be.w;
    *(float4*)(O + r * D_ + t * 4) = o;
}

// ---------------- launcher ----------------
extern "C" void kernel_launch(void* const* d_in, const int* in_sizes, int n_in,
                              void* d_out, int out_size)
{
    const float* x     = (const float*)d_in[0];
    const float* w_qkv = (const float*)d_in[1];
    const float* w_out = (const float*)d_in[2];
    const float* b_out = (const float*)d_in[3];
    const float* bt    = (const float*)d_in[4];
    const float* g1    = (const float*)d_in[5];
    const float* be1   = (const float*)d_in[6];
    const float* w1    = (const float*)d_in[7];
    const float* bf1   = (const float*)d_in[8];
    const float* w2    = (const float*)d_in[9];
    const float* bf2   = (const float*)d_in[10];
    const float* g2    = (const float*)d_in[11];
    const float* be2   = (const float*)d_in[12];
    float* out = (float*)d_out;

    float *qkv, *ctx, *x1, *hh, *tt;
    cudaGetSymbolAddress((void**)&qkv, g_qkv);
    cudaGetSymbolAddress((void**)&ctx, g_ctx);
    cudaGetSymbolAddress((void**)&x1,  g_x1);
    cudaGetSymbolAddress((void**)&hh,  g_h);
    cudaGetSymbolAddress((void**)&tt,  g_t);

    cudaFuncSetAttribute(flash_attn, cudaFuncAttributeMaxDynamicSharedMemorySize,
                         FA_SMEM_BYTES);

    // 1) qkv = x @ w_qkv
    gemm_tf32<0><<<dim3(3 * D_ / 128, M_ / 128), 128>>>(
        x, w_qkv, nullptr, qkv, D_, D_, 3 * D_, 3 * D_);

    // 2) fused attention -> ctx
    flash_attn<<<dim3(L_ / 128, B_ * H_), 256, FA_SMEM_BYTES>>>(qkv, bt, ctx);

    // 3) attn_out = ctx @ w_out + b_out
    gemm_tf32<1><<<dim3(D_ / 128, M_ / 128), 128>>>(
        ctx, w_out, b_out, tt, D_, D_, D_, D_);

    // 4) x1 = LN(x + attn_out)
    add_ln<<<M_, 256>>>(x, tt, g1, be1, x1);

    // 5) h = gelu(x1 @ w_ff1 + b_ff1)
    gemm_tf32<2><<<dim3(DFF_ / 128, M_ / 128), 128>>>(
        x1, w1, bf1, hh, D_, D_, DFF_, DFF_);

    // 6) ffn_out = h @ w_ff2 + b_ff2
    gemm_tf32<1><<<dim3(D_ / 128, M_ / 128), 128>>>(
        hh, w2, bf2, tt, DFF_, DFF_, D_, D_);

    // 7) out = LN(x1 + ffn_out)
    add_ln<<<M_, 256>>>(x1, tt, g2, be2, out);
}